// round 1
// baseline (speedup 1.0000x reference)
#include <cuda_runtime.h>
#include <stdint.h>

// ---------------------------------------------------------------------------
// FasterRCNN RPN proposal head: softmax -> top-4000 (exact jax.lax.top_k
// ordering: descending score bits, ascending-index tie-break) -> box decode ->
// greedy NMS (IoU 0.3), output [b(4000x4) | o(4000x2) | keep(4000)] as f32.
// ---------------------------------------------------------------------------

#define HF 512
#define WF 512
#define KA 9
#define NANCH (HF * WF * KA)       // 2359296
#define IMGW 16384.0f
#define IMGH 16384.0f
#define TOPK_N 4000
#define THR 0.5f
#define IOU_T 0.3f
#define NW 63                      // ceil(4000/64) suppression words per row
#define NBINS 65536
#define CAP 8192
#define BITS_BASE 0x3F000000u      // bits of 0.5f

// ---- scratch (static device globals: no allocation in kernel_launch) ------
__device__ uint32_t           d_hist[NBINS];
__device__ uint32_t           d_cutbin;
__device__ uint32_t           d_count;
__device__ unsigned long long d_keys[CAP];
__device__ unsigned long long d_sorted[TOPK_N];
__device__ float d_bx1[TOPK_N], d_by1[TOPK_N], d_bx2[TOPK_N], d_by2[TOPK_N], d_ar[TOPK_N];
__device__ int   d_valid[TOPK_N];
__device__ unsigned long long d_mask[TOPK_N * NW];
__device__ unsigned long long d_rnz[NW];   // bitmap: rows with any suppression bit

// p1 of 2-way softmax, matching jax.nn.softmax numerics (sub-max, expf, div).
__device__ __forceinline__ float score_p1(const float* __restrict__ obj, int i) {
    int cell = i / KA;
    int k    = i - cell * KA;
    const float* p = obj + (size_t)cell * (2 * KA) + 2 * k;
    float l0 = p[0], l1 = p[1];
    float m  = fmaxf(l0, l1);
    float e0 = expf(l0 - m);
    float e1 = expf(l1 - m);
    return e1 / (e0 + e1);
}

__global__ void k_zero() {
    int i = blockIdx.x * blockDim.x + threadIdx.x;
    if (i < NBINS)  d_hist[i] = 0u;
    if (i < CAP)    d_keys[i] = 0ull;
    if (i < TOPK_N) d_sorted[i] = 0ull;
    if (i < NW)     d_rnz[i] = 0ull;
    if (i == 0) { d_count = 0u; d_cutbin = 0u; }
}

__global__ void k_hist(const float* __restrict__ obj) {
    int i = blockIdx.x * blockDim.x + threadIdx.x;
    if (i >= NANCH) return;
    float s = score_p1(obj, i);
    if (s > THR) {
        uint32_t b = (__float_as_uint(s) - BITS_BASE) >> 7;
        if (b > (NBINS - 1)) b = NBINS - 1;
        atomicAdd(&d_hist[b], 1u);
    }
}

// Find smallest bin B such that count(bins >= B) >= TOPK_N.
__global__ void k_cutoff() {
    __shared__ uint32_t csum[256];
    int t = threadIdx.x;
    uint32_t s = 0;
    int base = t * 256;
    for (int b = 0; b < 256; b++) s += d_hist[base + b];
    csum[t] = s;
    __syncthreads();
    if (t == 0) {
        uint32_t acc = 0;
        int c;
        for (c = 255; c >= 0; c--) {
            if (acc + csum[c] >= TOPK_N) break;
            acc += csum[c];
        }
        uint32_t cut = 0;
        if (c >= 0) {
            int b;
            for (b = c * 256 + 255; b >= c * 256; b--) {
                acc += d_hist[b];
                if (acc >= TOPK_N) break;
            }
            if (b < c * 256) b = c * 256;
            cut = (uint32_t)b;
        }
        d_cutbin = cut;
    }
}

__global__ void k_compact(const float* __restrict__ obj) {
    int i = blockIdx.x * blockDim.x + threadIdx.x;
    if (i >= NANCH) return;
    float s = score_p1(obj, i);
    if (s > THR) {
        uint32_t sb = __float_as_uint(s);
        uint32_t b  = (sb - BITS_BASE) >> 7;
        if (b > (NBINS - 1)) b = NBINS - 1;
        if (b >= d_cutbin) {
            uint32_t pos = atomicAdd(&d_count, 1u);
            if (pos < CAP) {
                // key: score bits high (descending), ~idx low (ascending idx ties)
                d_keys[pos] = ((unsigned long long)sb << 32) |
                              (unsigned long long)(~(uint32_t)i);
            }
        }
    }
}

// Exact sort by ranking: rank = #keys strictly greater. Keys unique (idx in key).
__global__ void k_rank() {
    __shared__ unsigned long long tile[256];
    int t = threadIdx.x;
    int i = blockIdx.x * 256 + t;
    uint32_t cnt = d_count;
    if (cnt > CAP) cnt = CAP;
    unsigned long long mykey = (i < (int)cnt) ? d_keys[i] : 0ull;
    int rank = 0;
    int ntiles = ((int)cnt + 255) / 256;
    for (int tb = 0; tb < ntiles; tb++) {
        int j = tb * 256 + t;
        tile[t] = (j < (int)cnt) ? d_keys[j] : 0ull;
        __syncthreads();
        if (i < (int)cnt) {
#pragma unroll 16
            for (int u = 0; u < 256; u++) rank += (tile[u] > mykey) ? 1 : 0;
        }
        __syncthreads();
    }
    if (i < (int)cnt && rank < TOPK_N) d_sorted[rank] = mykey;
}

__global__ void k_gather(const float* __restrict__ obj,
                         const float* __restrict__ reg,
                         const float* __restrict__ anch,
                         float* __restrict__ out) {
    int r = blockIdx.x * blockDim.x + threadIdx.x;
    if (r >= TOPK_N) return;
    unsigned long long key = d_sorted[r];
    if (key == 0ull) {
        out[r * 4 + 0] = 0.f; out[r * 4 + 1] = 0.f; out[r * 4 + 2] = 0.f; out[r * 4 + 3] = 0.f;
        out[4 * TOPK_N + r * 2 + 0] = 0.f;
        out[4 * TOPK_N + r * 2 + 1] = 0.f;
        d_bx1[r] = d_by1[r] = d_bx2[r] = d_by2[r] = d_ar[r] = 0.f;
        d_valid[r] = 0;
        return;
    }
    uint32_t idx = ~((uint32_t)key);
    int cell = (int)(idx / KA);
    int k    = (int)(idx - (uint32_t)cell * KA);

    const float* po = obj + (size_t)cell * (2 * KA) + 2 * k;
    float l0 = po[0], l1 = po[1];
    float m  = fmaxf(l0, l1);
    float e0 = expf(l0 - m), e1 = expf(l1 - m);
    float den = e0 + e1;
    float p0 = e0 / den, p1 = e1 / den;

    const float* pr = reg + (size_t)cell * (4 * KA) + 4 * k;
    float r0 = pr[0], r1 = pr[1], r2 = pr[2], r3 = pr[3];

    const float* pa = anch + (size_t)idx * 4;
    float ax = pa[0], ay = pa[1], aw = pa[2], ah = pa[3];

    float cx = (ax + aw * 0.5f) + r0 * aw;
    float cy = (ay + ah * 0.5f) + r1 * ah;
    float w  = aw * expf(r2);
    float h  = ah * expf(r3);
    float bx = cx - w * 0.5f;
    float by = cy - h * 0.5f;
    float x1 = fminf(fmaxf(bx, 0.f), IMGW);
    float y1 = fminf(fmaxf(by, 0.f), IMGH);
    float x2 = fminf(fmaxf(bx + w, 0.f), IMGW);
    float y2 = fminf(fmaxf(by + h, 0.f), IMGH);
    float bw = x2 - x1, bh = y2 - y1;

    out[r * 4 + 0] = x1;
    out[r * 4 + 1] = y1;
    out[r * 4 + 2] = bw;
    out[r * 4 + 3] = bh;
    out[4 * TOPK_N + r * 2 + 0] = p0;
    out[4 * TOPK_N + r * 2 + 1] = p1;

    // NMS geometry exactly as reference: x2 = x1 + b[:,2] etc.
    d_bx1[r] = x1;
    d_by1[r] = y1;
    d_bx2[r] = x1 + bw;
    d_by2[r] = y1 + bh;
    d_ar[r]  = bw * bh;
    d_valid[r] = (p1 > THR) ? 1 : 0;
}

__global__ void k_mask() {
    __shared__ float sx1[64], sy1[64], sx2[64], sy2[64], sa[64];
    int cb = blockIdx.x;   // column block
    int rb = blockIdx.y;   // row block
    int t  = threadIdx.x;
    int cj = cb * 64 + t;
    if (cj < TOPK_N) {
        sx1[t] = d_bx1[cj]; sy1[t] = d_by1[cj];
        sx2[t] = d_bx2[cj]; sy2[t] = d_by2[cj];
        sa[t]  = d_ar[cj];
    }
    __syncthreads();
    int i = rb * 64 + t;
    if (i >= TOPK_N) return;
    float x1 = d_bx1[i], y1 = d_by1[i], x2 = d_bx2[i], y2 = d_by2[i], ar = d_ar[i];
    unsigned long long wbits = 0ull;
    int jmax = TOPK_N - cb * 64;
    if (jmax > 64) jmax = 64;
    for (int u = 0; u < jmax; u++) {
        int j = cb * 64 + u;
        if (j <= i) continue;
        float iw = fmaxf(fminf(x2, sx2[u]) - fmaxf(x1, sx1[u]), 0.f);
        float ih = fmaxf(fminf(y2, sy2[u]) - fmaxf(y1, sy1[u]), 0.f);
        float inter = iw * ih;
        float iou = inter / (ar + sa[u] - inter + 1e-8f);
        if (iou > IOU_T) wbits |= (1ull << u);
    }
    d_mask[(size_t)i * NW + cb] = wbits;
    if (wbits) atomicOr(&d_rnz[i >> 6], 1ull << (i & 63));
}

// Serial-in-principle NMS scan, but only over rows with nonzero masks.
// Bits are monotone and only set by earlier rows, so final state == per-step state.
__global__ void k_nms(float* __restrict__ out) {
    __shared__ unsigned long long remv[NW];
    int lane = threadIdx.x;
    for (int w = lane; w < NW; w += 32) remv[w] = 0ull;
    __syncwarp();
    for (int w = 0; w < NW; w++) {
        unsigned long long bits = d_rnz[w];
        while (bits) {
            int b = __ffsll((long long)bits) - 1;
            bits &= bits - 1ull;
            int i = w * 64 + b;
            unsigned long long cw = remv[w];
            bool keep = !((cw >> b) & 1ull) && d_valid[i];
            if (keep) {
                remv[lane] |= d_mask[(size_t)i * NW + lane];
                if (lane + 32 < NW) remv[lane + 32] |= d_mask[(size_t)i * NW + lane + 32];
            }
            __syncwarp();
        }
    }
    for (int i = lane; i < TOPK_N; i += 32) {
        bool kp = d_valid[i] && !((remv[i >> 6] >> (i & 63)) & 1ull);
        out[6 * TOPK_N + i] = kp ? 1.0f : 0.0f;
    }
}

extern "C" void kernel_launch(void* const* d_in, const int* in_sizes, int n_in,
                              void* d_out, int out_size) {
    (void)in_sizes; (void)n_in; (void)out_size;
    const float* obj  = (const float*)d_in[0];
    const float* reg  = (const float*)d_in[1];
    const float* anch = (const float*)d_in[2];
    float* out = (float*)d_out;

    k_zero   <<<(NBINS + 255) / 256, 256>>>();
    k_hist   <<<(NANCH + 255) / 256, 256>>>(obj);
    k_cutoff <<<1, 256>>>();
    k_compact<<<(NANCH + 255) / 256, 256>>>(obj);
    k_rank   <<<CAP / 256, 256>>>();
    k_gather <<<(TOPK_N + 127) / 128, 128>>>(obj, reg, anch, out);
    k_mask   <<<dim3(NW, NW), 64>>>();
    k_nms    <<<1, 32>>>(out);
}

// round 2
// speedup vs baseline: 1.4202x; 1.4202x over previous
#include <cuda_runtime.h>
#include <stdint.h>

// ---------------------------------------------------------------------------
// FasterRCNN RPN proposal head, round 2:
//  - single streaming pass: softmax p1 (1 expf, bit-exact), histogram on score
//    bits, spill candidates s>0.9 with full sort key (block-aggregated)
//  - parallel/coalesced cutoff search
//  - compact from spill (fallback full rescan if cutoff < 0.9)
//  - exact rank-by-counting sort on (score_bits, ~idx)
//  - box decode + IoU mask + NMS with all flagged mask rows staged in SMEM
// ---------------------------------------------------------------------------

#define HF 512
#define WF 512
#define KA 9
#define NANCH (HF * WF * KA)       // 2359296
#define IMGW 16384.0f
#define IMGH 16384.0f
#define TOPK_N 4000
#define THR 0.5f
#define IOU_T 0.3f
#define NW 63                      // ceil(4000/64) suppression words per row
#define NBINS 65536
#define CAP 16384
#define BITS_BASE 0x3F000000u      // bits of 0.5f
#define SPILL_S 0.9f
#define PREF_MIN_BIN 52430u        // bin(bits(0.9f)) + 2 safety
#define SPILLCAP 400000
#define RMAX 416                   // staged NMS rows (416*63*8 = 209664 B smem)

// ---- scratch (static device globals: no allocation in kernel_launch) ------
__device__ uint32_t           d_hist[NBINS];
__device__ uint32_t           d_cutbin;
__device__ uint32_t           d_count;
__device__ uint32_t           d_spillcount;
__device__ int                d_fallback;
__device__ unsigned long long d_spill[SPILLCAP];
__device__ unsigned long long d_keys[CAP];
__device__ unsigned long long d_sorted[TOPK_N];
__device__ float d_bx1[TOPK_N], d_by1[TOPK_N], d_bx2[TOPK_N], d_by2[TOPK_N], d_ar[TOPK_N];
__device__ int   d_valid[TOPK_N];
__device__ unsigned long long d_mask[TOPK_N * NW];
__device__ unsigned long long d_rnz[NW];   // bitmap: rows with any suppression bit

// p1 of 2-way softmax, bit-identical to jax.nn.softmax for 2 classes:
// exp of the max-side argument is exactly expf(0)=1.0f.
__device__ __forceinline__ float score_p1_pos(float l0, float l1) {
    // caller guarantees l1 > l0
    float x = expf(l0 - l1);
    return 1.0f / (x + 1.0f);
}

__global__ void k_zero() {
    int i = blockIdx.x * blockDim.x + threadIdx.x;
    if (i < NBINS)  d_hist[i] = 0u;
    if (i < TOPK_N) d_sorted[i] = 0ull;
    if (i < NW)     d_rnz[i] = 0ull;
    if (i == 0) { d_count = 0u; d_cutbin = 0u; d_spillcount = 0u; d_fallback = 0; }
}

// One streaming pass: histogram + spill of strong candidates (s > 0.9).
__global__ void k_pass1(const float* __restrict__ obj) {
    __shared__ unsigned long long stage[256];
    __shared__ uint32_t s_cnt, s_base;
    int t = threadIdx.x;
    int i = blockIdx.x * 256 + t;
    if (t == 0) s_cnt = 0u;
    __syncthreads();
    if (i < NANCH) {
        // obj layout (H,W,2K): logits for anchor i live at obj[2i], obj[2i+1]
        float2 l = ((const float2*)obj)[i];
        if (l.y > l.x) {
            float s = score_p1_pos(l.x, l.y);
            if (s > THR) {
                uint32_t sb = __float_as_uint(s);
                uint32_t b  = (sb - BITS_BASE) >> 7;
                if (b > (NBINS - 1)) b = NBINS - 1;
                atomicAdd(&d_hist[b], 1u);
                if (s > SPILL_S) {
                    uint32_t p = atomicAdd(&s_cnt, 1u);
                    stage[p] = ((unsigned long long)sb << 32) |
                               (unsigned long long)(~(uint32_t)i);
                }
            }
        }
    }
    __syncthreads();
    if (t == 0 && s_cnt) s_base = atomicAdd(&d_spillcount, s_cnt);
    __syncthreads();
    if (t < s_cnt) {
        uint32_t gp = s_base + t;
        if (gp < SPILLCAP) d_spill[gp] = stage[t];
    }
}

// Find smallest bin B such that count(bins >= B) >= TOPK_N. Fully parallel loads.
__global__ void k_cutoff() {
    __shared__ uint32_t csum[256];
    __shared__ uint32_t sfine[256];
    __shared__ int s_c;
    __shared__ uint32_t s_acc;
    int t = threadIdx.x;
    int warp = t >> 5, lane = t & 31;
    // coarse sums, coalesced: warp handles whole 256-bin chunks
    for (int c = warp; c < 256; c += 8) {
        uint32_t s = 0;
        for (int b = lane; b < 256; b += 32) s += d_hist[c * 256 + b];
        #pragma unroll
        for (int o = 16; o; o >>= 1) s += __shfl_down_sync(0xFFFFFFFFu, s, o);
        if (lane == 0) csum[c] = s;
    }
    __syncthreads();
    if (t == 0) {
        uint32_t acc = 0; int c;
        for (c = 255; c >= 0; c--) {
            if (acc + csum[c] >= TOPK_N) break;
            acc += csum[c];
        }
        s_c = c; s_acc = acc;
    }
    __syncthreads();
    if (s_c >= 0) sfine[t] = d_hist[s_c * 256 + t];
    __syncthreads();
    if (t == 0) {
        uint32_t cut = 0;
        if (s_c >= 0) {
            uint32_t acc = s_acc; int b;
            for (b = 255; b >= 0; b--) {
                acc += sfine[b];
                if (acc >= TOPK_N) break;
            }
            if (b < 0) b = 0;
            cut = (uint32_t)(s_c * 256 + b);
        }
        d_cutbin = cut;
        int fb = 0;
        if (cut < PREF_MIN_BIN) fb = 1;           // cutoff below spill prefilter
        if (d_spillcount > SPILLCAP) fb = 1;      // spill overflow
        d_fallback = fb;
    }
}

// Fast path: filter spilled candidates by cutoff bin.
__global__ void k_compact_spill() {
    if (d_fallback) return;
    uint32_t n = d_spillcount; if (n > SPILLCAP) n = SPILLCAP;
    uint32_t cut = d_cutbin;
    for (uint32_t i = blockIdx.x * blockDim.x + threadIdx.x; i < n;
         i += gridDim.x * blockDim.x) {
        unsigned long long key = d_spill[i];
        uint32_t sb = (uint32_t)(key >> 32);
        uint32_t b  = (sb - BITS_BASE) >> 7;
        if (b > (NBINS - 1)) b = NBINS - 1;
        if (b >= cut) {
            uint32_t p = atomicAdd(&d_count, 1u);
            if (p < CAP) d_keys[p] = key;
        }
    }
}

// Fallback path: full rescan (only runs if cutoff < 0.9 — never with this data).
__global__ void k_compact_full(const float* __restrict__ obj) {
    if (!d_fallback) return;
    uint32_t cut = d_cutbin;
    for (int i = blockIdx.x * blockDim.x + threadIdx.x; i < NANCH;
         i += gridDim.x * blockDim.x) {
        float2 l = ((const float2*)obj)[i];
        if (l.y > l.x) {
            float s = score_p1_pos(l.x, l.y);
            if (s > THR) {
                uint32_t sb = __float_as_uint(s);
                uint32_t b  = (sb - BITS_BASE) >> 7;
                if (b > (NBINS - 1)) b = NBINS - 1;
                if (b >= cut) {
                    uint32_t p = atomicAdd(&d_count, 1u);
                    if (p < CAP) d_keys[p] = ((unsigned long long)sb << 32) |
                                             (unsigned long long)(~(uint32_t)i);
                }
            }
        }
    }
}

// Exact sort by ranking: rank = #keys strictly greater. Keys unique (idx in key).
__global__ void k_rank() {
    __shared__ unsigned long long tile[256];
    int t = threadIdx.x;
    uint32_t cnt = d_count;
    if (cnt > CAP) cnt = CAP;
    if (blockIdx.x * 256 >= (int)cnt) return;
    int i = blockIdx.x * 256 + t;
    unsigned long long mykey = (i < (int)cnt) ? d_keys[i] : 0ull;
    int rank = 0;
    int ntiles = ((int)cnt + 255) / 256;
    for (int tb = 0; tb < ntiles; tb++) {
        int j = tb * 256 + t;
        tile[t] = (j < (int)cnt) ? d_keys[j] : 0ull;
        __syncthreads();
        if (i < (int)cnt) {
#pragma unroll 16
            for (int u = 0; u < 256; u++) rank += (tile[u] > mykey) ? 1 : 0;
        }
        __syncthreads();
    }
    if (i < (int)cnt && rank < TOPK_N) d_sorted[rank] = mykey;
}

__global__ void k_gather(const float* __restrict__ obj,
                         const float* __restrict__ reg,
                         const float* __restrict__ anch,
                         float* __restrict__ out) {
    int r = blockIdx.x * blockDim.x + threadIdx.x;
    if (r >= TOPK_N) return;
    unsigned long long key = d_sorted[r];
    if (key == 0ull) {
        out[r * 4 + 0] = 0.f; out[r * 4 + 1] = 0.f; out[r * 4 + 2] = 0.f; out[r * 4 + 3] = 0.f;
        out[4 * TOPK_N + r * 2 + 0] = 0.f;
        out[4 * TOPK_N + r * 2 + 1] = 0.f;
        d_bx1[r] = d_by1[r] = d_bx2[r] = d_by2[r] = d_ar[r] = 0.f;
        d_valid[r] = 0;
        return;
    }
    uint32_t idx = ~((uint32_t)key);

    float2 l = ((const float2*)obj)[idx];
    float p0, p1;
    if (l.y >= l.x) {            // m = l1: e0 = expf(l0-l1), e1 = 1.0f
        float x = expf(l.x - l.y);
        float den = x + 1.0f;
        p0 = x / den; p1 = 1.0f / den;
    } else {                     // m = l0: e0 = 1.0f, e1 = expf(l1-l0)
        float y = expf(l.y - l.x);
        float den = 1.0f + y;
        p0 = 1.0f / den; p1 = y / den;
    }

    float4 rg = ((const float4*)reg)[idx];
    float4 a  = ((const float4*)anch)[idx];
    float ax = a.x, ay = a.y, aw = a.z, ah = a.w;

    float cx = (ax + aw * 0.5f) + rg.x * aw;
    float cy = (ay + ah * 0.5f) + rg.y * ah;
    float w  = aw * expf(rg.z);
    float h  = ah * expf(rg.w);
    float bx = cx - w * 0.5f;
    float by = cy - h * 0.5f;
    float x1 = fminf(fmaxf(bx, 0.f), IMGW);
    float y1 = fminf(fmaxf(by, 0.f), IMGH);
    float x2 = fminf(fmaxf(bx + w, 0.f), IMGW);
    float y2 = fminf(fmaxf(by + h, 0.f), IMGH);
    float bw = x2 - x1, bh = y2 - y1;

    out[r * 4 + 0] = x1;
    out[r * 4 + 1] = y1;
    out[r * 4 + 2] = bw;
    out[r * 4 + 3] = bh;
    out[4 * TOPK_N + r * 2 + 0] = p0;
    out[4 * TOPK_N + r * 2 + 1] = p1;

    d_bx1[r] = x1;
    d_by1[r] = y1;
    d_bx2[r] = x1 + bw;
    d_by2[r] = y1 + bh;
    d_ar[r]  = bw * bh;
    d_valid[r] = (p1 > THR) ? 1 : 0;
}

__global__ void k_mask() {
    __shared__ float sx1[64], sy1[64], sx2[64], sy2[64], sa[64];
    int cb = blockIdx.x;   // column block
    int rb = blockIdx.y;   // row block
    int t  = threadIdx.x;
    int i  = rb * 64 + t;
    // block entirely at/below diagonal: no j>i possible -> write zero word
    if (cb * 64 + 63 <= rb * 64) {
        if (i < TOPK_N) d_mask[(size_t)i * NW + cb] = 0ull;
        return;
    }
    int cj = cb * 64 + t;
    if (cj < TOPK_N) {
        sx1[t] = d_bx1[cj]; sy1[t] = d_by1[cj];
        sx2[t] = d_bx2[cj]; sy2[t] = d_by2[cj];
        sa[t]  = d_ar[cj];
    }
    __syncthreads();
    if (i >= TOPK_N) return;
    float x1 = d_bx1[i], y1 = d_by1[i], x2 = d_bx2[i], y2 = d_by2[i], ar = d_ar[i];
    unsigned long long wbits = 0ull;
    int jmax = TOPK_N - cb * 64;
    if (jmax > 64) jmax = 64;
    for (int u = 0; u < jmax; u++) {
        int j = cb * 64 + u;
        if (j <= i) continue;
        float iw = fmaxf(fminf(x2, sx2[u]) - fmaxf(x1, sx1[u]), 0.f);
        float ih = fmaxf(fminf(y2, sy2[u]) - fmaxf(y1, sy1[u]), 0.f);
        float inter = iw * ih;
        float iou = inter / (ar + sa[u] - inter + 1e-8f);
        if (iou > IOU_T) wbits |= (1ull << u);
    }
    d_mask[(size_t)i * NW + cb] = wbits;
    if (wbits) atomicOr(&d_rnz[i >> 6], 1ull << (i & 63));
}

// NMS scan with all flagged rows' mask words staged in shared memory.
// Bits are monotone (j > i only), so final state == per-step state.
__global__ void k_nms(float* __restrict__ out) {
    extern __shared__ unsigned long long s_mask[];   // RMAX * NW words
    __shared__ unsigned long long s_rnz[NW], s_remv[NW], s_vb[NW];
    __shared__ int s_list[RMAX];
    __shared__ int s_wpref[NW];
    __shared__ int s_R;
    int t = threadIdx.x;  // 1024 threads

    if (t < NW) { s_rnz[t] = d_rnz[t]; s_remv[t] = 0ull; s_vb[t] = 0ull; }
    __syncthreads();
    if (t == 0) {
        int acc = 0;
        for (int w = 0; w < NW; w++) { s_wpref[w] = acc; acc += __popcll(s_rnz[w]); }
        s_R = acc;
    }
    for (int i = t; i < TOPK_N; i += 1024)
        if (d_valid[i]) atomicOr(&s_vb[i >> 6], 1ull << (i & 63));
    __syncthreads();
    if (t < NW) {
        unsigned long long bits = s_rnz[t];
        int slot = s_wpref[t];
        while (bits) {
            int b = __ffsll((long long)bits) - 1;
            bits &= bits - 1ull;
            if (slot < RMAX) s_list[slot] = t * 64 + b;
            slot++;
        }
    }
    __syncthreads();
    int Rc = s_R < RMAX ? s_R : RMAX;
    for (int e = t; e < Rc * NW; e += 1024) {
        int slot = e / NW;
        int c    = e - slot * NW;
        s_mask[e] = d_mask[(size_t)s_list[slot] * NW + c];
    }
    __syncthreads();

    if (t < 32) {
        int sc = 0;
        for (int w = 0; w < NW; w++) {
            unsigned long long bits = s_rnz[w];
            while (bits) {
                int b = __ffsll((long long)bits) - 1;
                bits &= bits - 1ull;
                int i = w * 64 + b;
                bool keep = ((s_vb[w] >> b) & 1ull) && !((s_remv[w] >> b) & 1ull);
                if (keep) {
                    if (sc < RMAX) {
                        const unsigned long long* src = &s_mask[(size_t)sc * NW];
                        s_remv[t] |= src[t];
                        if (t + 32 < NW) s_remv[t + 32] |= src[t + 32];
                    } else {
                        const unsigned long long* src = &d_mask[(size_t)i * NW];
                        s_remv[t] |= src[t];
                        if (t + 32 < NW) s_remv[t + 32] |= src[t + 32];
                    }
                    __syncwarp();
                }
                sc++;
            }
        }
    }
    __syncthreads();
    for (int i = t; i < TOPK_N; i += 1024) {
        bool kp = ((s_vb[i >> 6] >> (i & 63)) & 1ull) &&
                  !((s_remv[i >> 6] >> (i & 63)) & 1ull);
        out[6 * TOPK_N + i] = kp ? 1.0f : 0.0f;
    }
}

extern "C" void kernel_launch(void* const* d_in, const int* in_sizes, int n_in,
                              void* d_out, int out_size) {
    (void)in_sizes; (void)n_in; (void)out_size;
    const float* obj  = (const float*)d_in[0];
    const float* reg  = (const float*)d_in[1];
    const float* anch = (const float*)d_in[2];
    float* out = (float*)d_out;

    const int NMS_SMEM = RMAX * NW * (int)sizeof(unsigned long long);  // 209664
    cudaFuncSetAttribute(k_nms, cudaFuncAttributeMaxDynamicSharedMemorySize, NMS_SMEM);

    k_zero         <<<(NBINS + 255) / 256, 256>>>();
    k_pass1        <<<(NANCH + 255) / 256, 256>>>(obj);
    k_cutoff       <<<1, 256>>>();
    k_compact_spill<<<256, 256>>>();
    k_compact_full <<<2048, 256>>>(obj);
    k_rank         <<<CAP / 256, 256>>>();
    k_gather       <<<(TOPK_N + 127) / 128, 128>>>(obj, reg, anch, out);
    k_mask         <<<dim3(NW, NW), 64>>>();
    k_nms          <<<1, 1024, NMS_SMEM>>>(out);
}

// round 3
// speedup vs baseline: 1.5413x; 1.0853x over previous
#include <cuda_runtime.h>
#include <stdint.h>

// ---------------------------------------------------------------------------
// FasterRCNN RPN proposal head, round 3:
//  - grid-stride zero of all scratch incl. 2MB mask matrix
//  - single streaming pass (float4, 2 anchors/thread): hist + spill s>0.9
//  - parallel cutoff; merged compact (spill fast path / full rescan fallback)
//  - exact rank-by-counting sort on (score_bits, ~idx)
//  - box decode; upper-triangle-only IoU mask tiles
//  - NMS: register-resident suppression state in one warp, bulk skip of
//    suppressed/invalid rows, no syncwarp in the serial chain
// ---------------------------------------------------------------------------

#define HF 512
#define WF 512
#define KA 9
#define NANCH (HF * WF * KA)       // 2359296
#define IMGW 16384.0f
#define IMGH 16384.0f
#define TOPK_N 4000
#define THR 0.5f
#define IOU_T 0.3f
#define NW 63                      // ceil(4000/64) suppression words per row
#define NBINS 65536
#define CAP 16384
#define BITS_BASE 0x3F000000u      // bits of 0.5f
#define SPILL_S 0.9f
#define PREF_MIN_BIN 52430u        // bin(bits(0.9f)) + 2 safety
#define SPILLCAP 400000
#define RMAX 416                   // staged NMS rows (416*63*8 = 209664 B smem)

typedef unsigned long long ull;

// ---- scratch (static device globals) --------------------------------------
__device__ uint32_t d_hist[NBINS];
__device__ uint32_t d_cutbin;
__device__ uint32_t d_count;
__device__ uint32_t d_spillcount;
__device__ int      d_fallback;
__device__ ull      d_spill[SPILLCAP];
__device__ ull      d_keys[CAP];
__device__ ull      d_sorted[TOPK_N];
__device__ float d_bx1[TOPK_N], d_by1[TOPK_N], d_bx2[TOPK_N], d_by2[TOPK_N], d_ar[TOPK_N];
__device__ int   d_valid[TOPK_N];
__device__ ull   d_mask[TOPK_N * NW];
__device__ ull   d_rnz[NW];

// p1 of 2-way softmax, bit-identical to jax.nn.softmax for 2 classes
// (exp of the max-side argument is exactly expf(0)=1.0f). Caller: l1 > l0.
__device__ __forceinline__ float score_p1_pos(float l0, float l1) {
    float x = expf(l0 - l1);
    return 1.0f / (x + 1.0f);
}

__global__ void k_zero() {
    int tid = blockIdx.x * blockDim.x + threadIdx.x;
    int stride = gridDim.x * blockDim.x;
    for (int i = tid; i < TOPK_N * NW; i += stride) d_mask[i] = 0ull;
    for (int i = tid; i < NBINS; i += stride) d_hist[i] = 0u;
    for (int i = tid; i < TOPK_N; i += stride) d_sorted[i] = 0ull;
    if (tid < NW) d_rnz[tid] = 0ull;
    if (tid == 0) { d_count = 0u; d_cutbin = 0u; d_spillcount = 0u; d_fallback = 0; }
}

// One streaming pass: histogram + spill of strong candidates (s > 0.9).
// Two anchors per thread via float4.
__global__ void k_pass1(const float4* __restrict__ obj4) {
    __shared__ ull stage[512];
    __shared__ uint32_t s_cnt, s_base;
    int t = threadIdx.x;
    int i2 = blockIdx.x * 256 + t;
    if (t == 0) s_cnt = 0u;
    __syncthreads();
    if (i2 < NANCH / 2) {
        float4 v = obj4[i2];
        #pragma unroll
        for (int h = 0; h < 2; h++) {
            float l0 = h ? v.z : v.x;
            float l1 = h ? v.w : v.y;
            if (l1 > l0) {                       // equivalent to p1 > 0.5
                float s = score_p1_pos(l0, l1);
                uint32_t sb = __float_as_uint(s);
                uint32_t b  = (sb - BITS_BASE) >> 7;
                if (b > (NBINS - 1)) b = NBINS - 1;
                atomicAdd(&d_hist[b], 1u);
                if (s > SPILL_S) {
                    uint32_t p = atomicAdd(&s_cnt, 1u);
                    uint32_t idx = 2u * (uint32_t)i2 + (uint32_t)h;
                    stage[p] = ((ull)sb << 32) | (ull)(~idx);
                }
            }
        }
    }
    __syncthreads();
    if (t == 0 && s_cnt) s_base = atomicAdd(&d_spillcount, s_cnt);
    __syncthreads();
    for (int p = t; p < (int)s_cnt; p += 256) {
        uint32_t gp = s_base + p;
        if (gp < SPILLCAP) d_spill[gp] = stage[p];
    }
}

// Smallest bin B with count(bins >= B) >= TOPK_N.
__global__ void k_cutoff() {
    __shared__ uint32_t csum[256];
    __shared__ uint32_t sfine[256];
    __shared__ int s_c;
    __shared__ uint32_t s_acc;
    int t = threadIdx.x;
    int warp = t >> 5, lane = t & 31;
    for (int c = warp; c < 256; c += 8) {
        uint32_t s = 0;
        for (int b = lane; b < 256; b += 32) s += d_hist[c * 256 + b];
        #pragma unroll
        for (int o = 16; o; o >>= 1) s += __shfl_down_sync(0xFFFFFFFFu, s, o);
        if (lane == 0) csum[c] = s;
    }
    __syncthreads();
    if (t == 0) {
        uint32_t acc = 0; int c;
        for (c = 255; c >= 0; c--) {
            if (acc + csum[c] >= TOPK_N) break;
            acc += csum[c];
        }
        s_c = c; s_acc = acc;
    }
    __syncthreads();
    if (s_c >= 0) sfine[t] = d_hist[s_c * 256 + t];
    __syncthreads();
    if (t == 0) {
        uint32_t cut = 0;
        if (s_c >= 0) {
            uint32_t acc = s_acc; int b;
            for (b = 255; b >= 0; b--) {
                acc += sfine[b];
                if (acc >= TOPK_N) break;
            }
            if (b < 0) b = 0;
            cut = (uint32_t)(s_c * 256 + b);
        }
        d_cutbin = cut;
        int fb = 0;
        if (cut < PREF_MIN_BIN) fb = 1;
        if (d_spillcount > SPILLCAP) fb = 1;
        d_fallback = fb;
    }
}

// Merged compact: fast path filters the spill; fallback rescans everything.
__global__ void k_compact(const float4* __restrict__ obj4) {
    uint32_t cut = d_cutbin;
    int stride = gridDim.x * blockDim.x;
    int tid = blockIdx.x * blockDim.x + threadIdx.x;
    if (!d_fallback) {
        uint32_t n = d_spillcount; if (n > SPILLCAP) n = SPILLCAP;
        for (uint32_t i = tid; i < n; i += stride) {
            ull key = d_spill[i];
            uint32_t sb = (uint32_t)(key >> 32);
            uint32_t b  = (sb - BITS_BASE) >> 7;
            if (b > (NBINS - 1)) b = NBINS - 1;
            if (b >= cut) {
                uint32_t p = atomicAdd(&d_count, 1u);
                if (p < CAP) d_keys[p] = key;
            }
        }
    } else {
        for (int i2 = tid; i2 < NANCH / 2; i2 += stride) {
            float4 v = obj4[i2];
            #pragma unroll
            for (int h = 0; h < 2; h++) {
                float l0 = h ? v.z : v.x;
                float l1 = h ? v.w : v.y;
                if (l1 > l0) {
                    float s = score_p1_pos(l0, l1);
                    uint32_t sb = __float_as_uint(s);
                    uint32_t b  = (sb - BITS_BASE) >> 7;
                    if (b > (NBINS - 1)) b = NBINS - 1;
                    if (b >= cut) {
                        uint32_t p = atomicAdd(&d_count, 1u);
                        uint32_t idx = 2u * (uint32_t)i2 + (uint32_t)h;
                        if (p < CAP) d_keys[p] = ((ull)sb << 32) | (ull)(~idx);
                    }
                }
            }
        }
    }
}

// Exact sort by ranking: rank = #keys strictly greater. Keys unique.
__global__ void k_rank() {
    __shared__ ull tile[256];
    int t = threadIdx.x;
    uint32_t cnt = d_count;
    if (cnt > CAP) cnt = CAP;
    if (blockIdx.x * 256 >= (int)cnt) return;
    int i = blockIdx.x * 256 + t;
    ull mykey = (i < (int)cnt) ? d_keys[i] : 0ull;
    int rank = 0;
    int ntiles = ((int)cnt + 255) / 256;
    for (int tb = 0; tb < ntiles; tb++) {
        int j = tb * 256 + t;
        tile[t] = (j < (int)cnt) ? d_keys[j] : 0ull;
        __syncthreads();
        if (i < (int)cnt) {
#pragma unroll 16
            for (int u = 0; u < 256; u++) rank += (tile[u] > mykey) ? 1 : 0;
        }
        __syncthreads();
    }
    if (i < (int)cnt && rank < TOPK_N) d_sorted[rank] = mykey;
}

__global__ void k_gather(const float* __restrict__ obj,
                         const float* __restrict__ reg,
                         const float* __restrict__ anch,
                         float* __restrict__ out) {
    int r = blockIdx.x * blockDim.x + threadIdx.x;
    if (r >= TOPK_N) return;
    ull key = d_sorted[r];
    if (key == 0ull) {
        out[r * 4 + 0] = 0.f; out[r * 4 + 1] = 0.f; out[r * 4 + 2] = 0.f; out[r * 4 + 3] = 0.f;
        out[4 * TOPK_N + r * 2 + 0] = 0.f;
        out[4 * TOPK_N + r * 2 + 1] = 0.f;
        d_bx1[r] = d_by1[r] = d_bx2[r] = d_by2[r] = d_ar[r] = 0.f;
        d_valid[r] = 0;
        return;
    }
    uint32_t idx = ~((uint32_t)key);

    float2 l = ((const float2*)obj)[idx];
    float p0, p1;
    if (l.y >= l.x) {
        float x = expf(l.x - l.y);
        float den = x + 1.0f;
        p0 = x / den; p1 = 1.0f / den;
    } else {
        float y = expf(l.y - l.x);
        float den = 1.0f + y;
        p0 = 1.0f / den; p1 = y / den;
    }

    float4 rg = ((const float4*)reg)[idx];
    float4 a  = ((const float4*)anch)[idx];
    float ax = a.x, ay = a.y, aw = a.z, ah = a.w;

    float cx = (ax + aw * 0.5f) + rg.x * aw;
    float cy = (ay + ah * 0.5f) + rg.y * ah;
    float w  = aw * expf(rg.z);
    float h  = ah * expf(rg.w);
    float bx = cx - w * 0.5f;
    float by = cy - h * 0.5f;
    float x1 = fminf(fmaxf(bx, 0.f), IMGW);
    float y1 = fminf(fmaxf(by, 0.f), IMGH);
    float x2 = fminf(fmaxf(bx + w, 0.f), IMGW);
    float y2 = fminf(fmaxf(by + h, 0.f), IMGH);
    float bw = x2 - x1, bh = y2 - y1;

    out[r * 4 + 0] = x1;
    out[r * 4 + 1] = y1;
    out[r * 4 + 2] = bw;
    out[r * 4 + 3] = bh;
    out[4 * TOPK_N + r * 2 + 0] = p0;
    out[4 * TOPK_N + r * 2 + 1] = p1;

    d_bx1[r] = x1;
    d_by1[r] = y1;
    d_bx2[r] = x1 + bw;
    d_by2[r] = y1 + bh;
    d_ar[r]  = bw * bh;
    d_valid[r] = (p1 > THR) ? 1 : 0;
}

__global__ void k_mask() {
    __shared__ float sx1[64], sy1[64], sx2[64], sy2[64], sa[64];
    int cb = blockIdx.x;   // column block
    int rb = blockIdx.y;   // row block
    if (cb < rb) return;   // below diagonal: words pre-zeroed in k_zero
    int t  = threadIdx.x;
    int i  = rb * 64 + t;
    int cj = cb * 64 + t;
    if (cj < TOPK_N) {
        sx1[t] = d_bx1[cj]; sy1[t] = d_by1[cj];
        sx2[t] = d_bx2[cj]; sy2[t] = d_by2[cj];
        sa[t]  = d_ar[cj];
    }
    __syncthreads();
    if (i >= TOPK_N) return;
    float x1 = d_bx1[i], y1 = d_by1[i], x2 = d_bx2[i], y2 = d_by2[i], ar = d_ar[i];
    ull wbits = 0ull;
    int jmax = TOPK_N - cb * 64;
    if (jmax > 64) jmax = 64;
    for (int u = 0; u < jmax; u++) {
        int j = cb * 64 + u;
        if (j <= i) continue;
        float iw = fmaxf(fminf(x2, sx2[u]) - fmaxf(x1, sx1[u]), 0.f);
        float ih = fmaxf(fminf(y2, sy2[u]) - fmaxf(y1, sy1[u]), 0.f);
        float inter = iw * ih;
        float iou = inter / (ar + sa[u] - inter + 1e-8f);
        if (iou > IOU_T) wbits |= (1ull << u);
    }
    if (wbits) {
        d_mask[(size_t)i * NW + cb] = wbits;
        atomicOr(&d_rnz[i >> 6], 1ull << (i & 63));
    }
}

// NMS scan. Suppression words live in warp-0 registers (lane l: words l, l+32).
// Per 64-row word: act = rnz & valid & ~remv. Kept rows OR their staged mask
// into lane registers; same-word suppressions folded via the mask's own word.
// No syncwarp in the serial chain.
__global__ void k_nms(float* __restrict__ out) {
    extern __shared__ ull s_mask[];   // RMAX * NW
    __shared__ ull s_rnz[NW], s_remv[NW], s_vb[NW];
    __shared__ int s_list[RMAX];
    __shared__ int s_wpref[NW];
    __shared__ int s_R;
    int t = threadIdx.x;  // 1024 threads

    if (t < NW) { s_rnz[t] = d_rnz[t]; s_vb[t] = 0ull; }
    __syncthreads();
    if (t == 0) {
        int acc = 0;
        for (int w = 0; w < NW; w++) { s_wpref[w] = acc; acc += __popcll(s_rnz[w]); }
        s_R = acc;
    }
    for (int i = t; i < TOPK_N; i += 1024)
        if (d_valid[i]) atomicOr(&s_vb[i >> 6], 1ull << (i & 63));
    __syncthreads();
    if (t < NW) {
        ull bits = s_rnz[t];
        int slot = s_wpref[t];
        while (bits) {
            int b = __ffsll((long long)bits) - 1;
            bits &= bits - 1ull;
            if (slot < RMAX) s_list[slot] = t * 64 + b;
            slot++;
        }
    }
    __syncthreads();
    int Rc = s_R < RMAX ? s_R : RMAX;
    for (int e = t; e < Rc * NW; e += 1024) {
        int slot = e / NW;
        int c    = e - slot * NW;
        s_mask[e] = d_mask[(size_t)s_list[slot] * NW + c];
    }
    __syncthreads();

    if (t < 32) {
        int l = t;
        ull r0 = 0ull, r1 = 0ull;     // suppression words l and l+32
        for (int w = 0; w < NW; w++) {
            ull v0 = __shfl_sync(0xFFFFFFFFu, r0, w & 31);
            ull v1 = __shfl_sync(0xFFFFFFFFu, r1, w & 31);
            ull remw = (w < 32) ? v0 : v1;
            ull act = s_rnz[w] & s_vb[w] & ~remw;
            while (act) {
                int b = __ffsll((long long)act) - 1;
                act &= act - 1ull;
                int slot = s_wpref[w] +
                           __popcll(s_rnz[w] & ((1ull << b) - 1ull));
                const ull* src = (slot < RMAX)
                    ? &s_mask[(size_t)slot * NW]
                    : &d_mask[(size_t)(w * 64 + b) * NW];
                r0 |= src[l];
                if (l + 32 < NW) r1 |= src[l + 32];
                act &= ~src[w];           // suppressions within this word
            }
        }
        s_remv[l] = r0;
        if (l + 32 < NW) s_remv[l + 32] = r1;
    }
    __syncthreads();
    for (int i = t; i < TOPK_N; i += 1024) {
        bool kp = ((s_vb[i >> 6] >> (i & 63)) & 1ull) &&
                  !((s_remv[i >> 6] >> (i & 63)) & 1ull);
        out[6 * TOPK_N + i] = kp ? 1.0f : 0.0f;
    }
}

extern "C" void kernel_launch(void* const* d_in, const int* in_sizes, int n_in,
                              void* d_out, int out_size) {
    (void)in_sizes; (void)n_in; (void)out_size;
    const float* obj  = (const float*)d_in[0];
    const float* reg  = (const float*)d_in[1];
    const float* anch = (const float*)d_in[2];
    float* out = (float*)d_out;

    const int NMS_SMEM = RMAX * NW * (int)sizeof(ull);  // 209664
    cudaFuncSetAttribute(k_nms, cudaFuncAttributeMaxDynamicSharedMemorySize, NMS_SMEM);

    k_zero   <<<512, 256>>>();
    k_pass1  <<<(NANCH / 2 + 255) / 256, 256>>>((const float4*)obj);
    k_cutoff <<<1, 256>>>();
    k_compact<<<512, 256>>>((const float4*)obj);
    k_rank   <<<CAP / 256, 256>>>();
    k_gather <<<(TOPK_N + 127) / 128, 128>>>(obj, reg, anch, out);
    k_mask   <<<dim3(NW, NW), 64>>>();
    k_nms    <<<1, 1024, NMS_SMEM>>>(out);
}